// round 3
// baseline (speedup 1.0000x reference)
#include <cuda_runtime.h>
#include <math.h>

// Geometry: 64 images of 512*512*3 = 786432 floats (3 MB each)
#define N_IMG 64
#define IMG_ELEMS 786432
#define IMG_VEC4 196608            // IMG_ELEMS/4
#define CHUNKS_PER_IMG 16
#define IMGS_PER_WAVE 8
#define NUM_BLOCKS (CHUNKS_PER_IMG * IMGS_PER_WAVE)   // 128 (all wave-1 resident on 148 SMs)
#define NUM_ITERS (N_IMG / IMGS_PER_WAVE)             // 8
#define CHUNK_VEC4 (IMG_VEC4 / CHUNKS_PER_IMG)        // 12288 float4 = 196608 bytes
#define THREADS 512
#define SMEM_BYTES (CHUNK_VEC4 * 16)                  // 196608

// Persistent device scratch (no allocations allowed)
__device__ float2 g_partials[N_IMG][CHUNKS_PER_IMG];
__device__ float2 g_ss[N_IMG];      // (scale, shift)
__device__ int    g_cnt[N_IMG];     // zero-initialized; self-resetting per launch

__device__ __forceinline__ int ld_acq(const int* p) {
    int v;
    asm volatile("ld.acquire.gpu.s32 %0, [%1];" : "=r"(v) : "l"(p) : "memory");
    return v;
}

__global__ __launch_bounds__(THREADS, 1)
void fused_standardize_kernel(const float4* __restrict__ in, float4* __restrict__ out) {
    extern __shared__ float4 sh[];                 // 196608 bytes: chunk cache
    __shared__ float2 warp_red[THREADS / 32];
    __shared__ float2 sh_ss;

    const int grp = blockIdx.x / CHUNKS_PER_IMG;   // 0..7  (which image of the wave)
    const int c   = blockIdx.x % CHUNKS_PER_IMG;   // 0..15 (chunk within image)
    const int tid  = threadIdx.x;
    const int lane = tid & 31, wid = tid >> 5;

    for (int it = 0; it < NUM_ITERS; ++it) {
        const int img = it * IMGS_PER_WAVE + grp;
        const size_t base = (size_t)img * IMG_VEC4 + (size_t)c * CHUNK_VEC4;

        // ---- Phase 1: stream chunk gmem -> smem, accumulating sum / sumsq ----
        float s = 0.f, sq = 0.f;
        #pragma unroll 8
        for (int j = tid; j < CHUNK_VEC4; j += THREADS) {
            float4 v = __ldcs(in + base + j);      // read-once: evict-first
            sh[j] = v;
            s  += (v.x + v.y) + (v.z + v.w);
            sq += (v.x * v.x + v.y * v.y) + (v.z * v.z + v.w * v.w);
        }

        // ---- Block tree reduction (deterministic) ----
        #pragma unroll
        for (int off = 16; off > 0; off >>= 1) {
            s  += __shfl_down_sync(0xffffffffu, s,  off);
            sq += __shfl_down_sync(0xffffffffu, sq, off);
        }
        if (lane == 0) warp_red[wid] = make_float2(s, sq);
        __syncthreads();
        if (wid == 0) {
            float2 v = (lane < THREADS / 32) ? warp_red[lane] : make_float2(0.f, 0.f);
            s = v.x; sq = v.y;
            #pragma unroll
            for (int off = 8; off > 0; off >>= 1) {
                s  += __shfl_down_sync(0xffffffffu, s,  off);
                sq += __shfl_down_sync(0xffffffffu, sq, off);
            }
            if (lane == 0) {
                g_partials[img][c] = make_float2(s, sq);
                __threadfence();                    // release partials
                atomicAdd(&g_cnt[img], 1);          // arrivals 1..16
            }
        }

        // ---- Phase 2: per-image stats rendezvous ----
        if (tid == 0) {
            if (c == 0) {
                while (ld_acq(&g_cnt[img]) < CHUNKS_PER_IMG) { /* spin */ }
                float ts = 0.f, tq = 0.f;
                #pragma unroll
                for (int k = 0; k < CHUNKS_PER_IMG; ++k) {   // fixed order -> deterministic
                    float2 p = g_partials[img][k];
                    ts += p.x; tq += p.y;
                }
                const float inv_n = 1.0f / (float)IMG_ELEMS;
                float mean = ts * inv_n;
                float var  = tq * inv_n - mean * mean;
                float stddev = sqrtf(fmaxf(var, 0.0f));
                const float min_std = 1.0f / sqrtf((float)IMG_ELEMS);
                float scale = 1.0f / fmaxf(stddev, min_std);
                float2 ss = make_float2(scale, -mean * scale);
                g_ss[img] = ss;
                __threadfence();                    // release ss
                atomicAdd(&g_cnt[img], 1);          // cnt -> 17: ready
                sh_ss = ss;
            } else {
                while (ld_acq(&g_cnt[img]) < CHUNKS_PER_IMG + 1) { /* spin */ }
                sh_ss = g_ss[img];
            }
        }
        __syncthreads();
        const float scale = sh_ss.x, shift = sh_ss.y;

        // ---- Phase 3: apply from smem, write out ----
        #pragma unroll 8
        for (int j = tid; j < CHUNK_VEC4; j += THREADS) {
            float4 v = sh[j];                      // each thread re-reads its own writes
            float4 r;
            r.x = fmaf(v.x, scale, shift);
            r.y = fmaf(v.y, scale, shift);
            r.z = fmaf(v.z, scale, shift);
            r.w = fmaf(v.w, scale, shift);
            __stcs(out + base + j, r);             // streaming store
        }
        __syncthreads();

        // ---- Done-arrival; 33rd arrival resets counter for next launch ----
        if (tid == 0) {
            int old = atomicAdd(&g_cnt[img], 1);   // arrivals 18..33
            if (old == 2 * CHUNKS_PER_IMG) g_cnt[img] = 0;
        }
    }
}

extern "C" void kernel_launch(void* const* d_in, const int* in_sizes, int n_in,
                              void* d_out, int out_size) {
    const float4* in = (const float4*)d_in[0];
    float4* out = (float4*)d_out;

    cudaFuncSetAttribute(fused_standardize_kernel,
                         cudaFuncAttributeMaxDynamicSharedMemorySize, SMEM_BYTES);
    fused_standardize_kernel<<<NUM_BLOCKS, THREADS, SMEM_BYTES>>>(in, out);
}